// round 12
// baseline (speedup 1.0000x reference)
#include <cuda_runtime.h>
#include <cstdint>

// ---------------------------------------------------------------- constants
#define C_IN   128
#define N_HEAD 8
#define IMG_H  192
#define IMG_W  192
#define NPIX   (IMG_H * IMG_W)     // 36864
#define PW     200                 // padded row stride (floats)
#define PH     194                 // padded rows
#define PVP    (PH * PW)           // 38800 floats per plane
#define TEMPER_INV (1.0f / 16.0f)

// scratch (device globals — allocation-free per harness rules)
__device__ float g_v[256 * PVP];        // 39.7 MB, padded planes, x-offset +2
__device__ float g_s[N_HEAD * PVP];     // 1.24 MB, padded planes, x-offset +2
__device__ uint4 g_wfrag[6 * 4096];     // 384 KB: W in A-fragment form, stage order

// ---------------------------------------------------------------- SMEM map
#define SM_X     0            // X^T B-fragments: 64 KB
#define SM_W0    65536        // W A-fragments buffer 0: 64 KB
#define SM_W1    131072       // W A-fragments buffer 1: 64 KB
#define SM_TOTAL 196608

// ---------------------------------------------------------------- primitives
__device__ __forceinline__ uint32_t f2tf32(float f) {
    uint32_t r;
    asm("cvt.rna.tf32.f32 %0, %1;" : "=r"(r) : "f"(f));
    return r;
}

__device__ __forceinline__ void mma_tf32(float c[4], const uint32_t a[4],
                                         uint32_t b0, uint32_t b1) {
    asm volatile(
        "mma.sync.aligned.m16n8k8.row.col.f32.tf32.tf32.f32 "
        "{%0,%1,%2,%3}, {%4,%5,%6,%7}, {%8,%9}, {%0,%1,%2,%3};"
        : "+f"(c[0]), "+f"(c[1]), "+f"(c[2]), "+f"(c[3])
        : "r"(a[0]), "r"(a[1]), "r"(a[2]), "r"(a[3]), "r"(b0), "r"(b1));
}

// X^T tile (128 pixels, 128 chans) -> B-fragment-major smem.
__device__ __forceinline__ void loadX_frag(const float* __restrict__ xt,
                                           char* buf, int tid) {
    const int lane = tid & 31, kstep = tid >> 5;
    const int n = lane >> 2, kc = lane & 3;
#pragma unroll
    for (int pixgrp = 0; pixgrp < 16; pixgrp++) {
        const int pix = pixgrp * 8 + n;
        const int ch  = kstep * 8 + kc;
        uint32_t b0 = f2tf32(xt[(size_t)ch * NPIX + pix]);
        uint32_t b1 = f2tf32(xt[(size_t)(ch + 4) * NPIX + pix]);
        *(uint2*)(buf + ((pixgrp * 16 + kstep) * 32 + lane) * 8) = make_uint2(b0, b1);
    }
}

// stage W fragments: plain coalesced copy from pre-converted global array
__device__ __forceinline__ void loadW_copy(int s, char* buf, int tid) {
    const uint4* __restrict__ src = g_wfrag + s * 4096;
    uint4* dst = (uint4*)buf;
#pragma unroll
    for (int i = 0; i < 8; i++)
        dst[tid + i * 512] = src[tid + i * 512];
}

// C[2][4][4] += A(Abuf)[128x128] @ B(Bbuf)[128pix x 128k]^T for this warp tile.
__device__ __forceinline__ void gemm_tf32(const char* Abuf, const char* Bbuf,
                                          float C[2][4][4],
                                          int wr, int wc, int lane) {
#pragma unroll 4
    for (int kstep = 0; kstep < 16; kstep++) {
        uint32_t a[2][4];
#pragma unroll
        for (int tm = 0; tm < 2; tm++)
            *(uint4*)a[tm] =
                *(const uint4*)(Abuf + (((wr * 2 + tm) * 16 + kstep) * 32 + lane) * 16);
        uint32_t b[4][2];
#pragma unroll
        for (int tn = 0; tn < 4; tn++)
            *(uint2*)b[tn] =
                *(const uint2*)(Bbuf + (((wc * 4 + tn) * 16 + kstep) * 32 + lane) * 8);
#pragma unroll
        for (int tm = 0; tm < 2; tm++)
#pragma unroll
            for (int tn = 0; tn < 4; tn++)
                mma_tf32(C[tm][tn], a[tm], b[tn][0], b[tn][1]);
    }
}

__device__ __forceinline__ void zeroC(float C[2][4][4]) {
#pragma unroll
    for (int i = 0; i < 2; i++)
#pragma unroll
        for (int j = 0; j < 4; j++)
#pragma unroll
            for (int m = 0; m < 4; m++) C[i][j][m] = 0.0f;
}

// fused score epilogue -> padded per-head s plane (x-offset +2)
__device__ __forceinline__ void epi_s(const float C0[2][4][4], const float C1[2][4][4],
                                      int h, int p0, int wc, int lane) {
#pragma unroll
    for (int tn = 0; tn < 4; tn++) {
        float s0 = 0.0f, s1 = 0.0f;
#pragma unroll
        for (int tm = 0; tm < 2; tm++) {
            s0 += C0[tm][tn][0] * C1[tm][tn][0] + C0[tm][tn][2] * C1[tm][tn][2];
            s1 += C0[tm][tn][1] * C1[tm][tn][1] + C0[tm][tn][3] * C1[tm][tn][3];
        }
#pragma unroll
        for (int d = 4; d < 32; d <<= 1) {
            s0 += __shfl_xor_sync(0xffffffffu, s0, d);
            s1 += __shfl_xor_sync(0xffffffffu, s1, d);
        }
        if (lane < 4) {
            const int pix = p0 + wc * 32 + tn * 8 + lane * 2;
            const int y = pix / IMG_W, xx = pix - y * IMG_W;     // xx even
            *(float2*)&g_s[(size_t)h * PVP + (size_t)(y + 1) * PW + (xx + 2)] =
                make_float2(s0 * TEMPER_INV, s1 * TEMPER_INV);
        }
    }
}

// v epilogue: padded channel planes (x-offset +2 keeps 8B alignment)
__device__ __forceinline__ void sto_v(const float C[2][4][4], int cb,
                                      int p0, int wr, int wc, int lane) {
#pragma unroll
    for (int tm = 0; tm < 2; tm++)
#pragma unroll
        for (int tn = 0; tn < 4; tn++) {
            const int chan = cb + wr * 32 + tm * 16 + (lane >> 2);
            const int pix  = p0 + wc * 32 + tn * 8 + (lane & 3) * 2;
            const int y = pix / IMG_W, xx = pix - y * IMG_W;     // xx even
            float* vp = g_v + (size_t)chan * PVP + (size_t)(y + 1) * PW + (xx + 2);
            *(float2*)vp = make_float2(C[tm][tn][0], C[tm][tn][1]);
            *(float2*)(vp + (size_t)8 * PVP) = make_float2(C[tm][tn][2], C[tm][tn][3]);
        }
}

// ---------------------------------------------------------------- kernel 0
// W fp32 -> tf32 A-fragment array, stage order:
//   s=0: wq[0:128]  s=1: wk[0:128]  s=2: wq[128:256]
//   s=3: wk[128:256]  s=4: wv[0:128]  s=5: wv[128:256]
__global__ void __launch_bounds__(512)
prep_w(const float* __restrict__ wq,
       const float* __restrict__ wk,
       const float* __restrict__ wv)
{
    const int s = blockIdx.x;            // 0..5
    const int rowgrp = blockIdx.y;       // 0..7
    const float* mat = (s == 0 || s == 2) ? wq : (s == 1 || s == 3) ? wk : wv;
    const int off = (s == 2 || s == 3 || s == 5) ? 16384 : 0;

    const int tid = threadIdx.x;
    const int lane = tid & 31, kstep = tid >> 5;
    const int r = lane >> 2, c = lane & 3;

    const float* p = mat + off + (rowgrp * 16 + r) * C_IN + kstep * 8 + c;
    g_wfrag[s * 4096 + (rowgrp * 16 + kstep) * 32 + lane] =
        make_uint4(f2tf32(p[0]), f2tf32(p[8 * C_IN]),
                   f2tf32(p[4]), f2tf32(p[8 * C_IN + 4]));
}

// ---------------------------------------------------------------- kernel 1
// one CTA per 128-pixel tile; 6 double-buffered weight stages (copies of
// pre-converted fragments). First 264 CTAs also zero the padded borders.
__global__ void __launch_bounds__(512, 1)
proj_fused(const float* __restrict__ x,
           const float* __restrict__ wq,
           const float* __restrict__ wk,
           const float* __restrict__ wv)
{
    extern __shared__ char smem[];
    const int tid  = threadIdx.x;
    const int lane = tid & 31;
    const int wid  = tid >> 5;
    const int wr   = wid >> 2;     // 32-channel row group
    const int wc   = wid & 3;      // 32-pixel col group
    const int p0   = blockIdx.x * 128;

    // ---- folded border zeroing
    {
        const int bx = blockIdx.x;
        float* plane = (bx < 256) ? (g_v + (size_t)bx * PVP)
                     : (bx < 264) ? (g_s + (size_t)(bx - 256) * PVP)
                     : nullptr;
        if (plane) {
            if (tid < 200) {
                plane[tid] = 0.0f;
                plane[(size_t)193 * PW + tid] = 0.0f;
            } else if (tid >= 256 && tid < 448) {
                const int r = tid - 255;                 // 1..192
                plane[(size_t)r * PW + 1]   = 0.0f;
                plane[(size_t)r * PW + 194] = 0.0f;
            }
        }
    }

    loadX_frag(x + p0, smem + SM_X, tid);
    loadW_copy(0, smem + SM_W0, tid);
    __syncthreads();

    float C0[2][4][4], C1[2][4][4];

    // stage 0: q chans 0..127  (buf0); prefetch stage1 -> buf1
    loadW_copy(1, smem + SM_W1, tid);
    zeroC(C0);
    gemm_tf32(smem + SM_W0, smem + SM_X, C0, wr, wc, lane);
    __syncthreads();

    // stage 1: k chans 0..127  (buf1); prefetch stage2 -> buf0
    loadW_copy(2, smem + SM_W0, tid);
    zeroC(C1);
    gemm_tf32(smem + SM_W1, smem + SM_X, C1, wr, wc, lane);
    epi_s(C0, C1, wr, p0, wc, lane);
    __syncthreads();

    // stage 2: q chans 128..255 (buf0); prefetch stage3 -> buf1
    loadW_copy(3, smem + SM_W1, tid);
    zeroC(C0);
    gemm_tf32(smem + SM_W0, smem + SM_X, C0, wr, wc, lane);
    __syncthreads();

    // stage 3: k chans 128..255 (buf1); prefetch stage4 -> buf0
    loadW_copy(4, smem + SM_W0, tid);
    zeroC(C1);
    gemm_tf32(smem + SM_W1, smem + SM_X, C1, wr, wc, lane);
    epi_s(C0, C1, 4 + wr, p0, wc, lane);
    __syncthreads();

    // stage 4: v chans 0..127 (buf0); prefetch stage5 -> buf1
    loadW_copy(5, smem + SM_W1, tid);
    zeroC(C0);
    gemm_tf32(smem + SM_W0, smem + SM_X, C0, wr, wc, lane);
    sto_v(C0, 0, p0, wr, wc, lane);
    __syncthreads();

    // stage 5: v chans 128..255 (buf1)
    zeroC(C0);
    gemm_tf32(smem + SM_W1, smem + SM_X, C0, wr, wc, lane);
    sto_v(C0, 128, p0, wr, wc, lane);
}

// ---------------------------------------------------------------- kernel 2
// vectorized attn, channel-split for occupancy: grid (48, 8, 4).
// R8 register version (regs=64, no spills) — proven 22.7 us.
__global__ void __launch_bounds__(192)
attn_kernel(float* __restrict__ out)
{
    const int tid = threadIdx.x;
    const int tx  = tid % 48;              // 48 threads per image row
    const int ty  = tid / 48;              // 4 rows per block
    const int y   = blockIdx.x * 4 + ty;
    const int h   = blockIdx.y;
    const int cg  = blockIdx.z * 8;        // channel group base
    const int px0 = tx * 4;

    // ---- s window: 3 rows x 8 cols
    float sf[3][8];
    {
        const float* sp = g_s + (size_t)h * PVP + (size_t)y * PW + px0;
#pragma unroll
        for (int dy = 0; dy < 3; dy++) {
            float4 a = *(const float4*)(sp + (size_t)dy * PW);
            float4 b = *(const float4*)(sp + (size_t)dy * PW + 4);
            sf[dy][0] = a.x; sf[dy][1] = a.y; sf[dy][2] = a.z; sf[dy][3] = a.w;
            sf[dy][4] = b.x; sf[dy][5] = b.y; sf[dy][6] = b.z; sf[dy][7] = b.w;
        }
    }

    // ---- softmax weights for the 4 pixels
    float w[4][9];
#pragma unroll
    for (int i = 0; i < 4; i++) {
        float m = sf[0][i + 1];
#pragma unroll
        for (int dy = 0; dy < 3; dy++)
#pragma unroll
            for (int dx = 0; dx < 3; dx++)
                m = fmaxf(m, sf[dy][i + dx + 1]);
        float sum = 0.0f;
#pragma unroll
        for (int dy = 0; dy < 3; dy++)
#pragma unroll
            for (int dx = 0; dx < 3; dx++) {
                float e = __expf(sf[dy][i + dx + 1] - m);
                w[i][dy * 3 + dx] = e;
                sum += e;
            }
        const float inv = 1.0f / sum;
#pragma unroll
        for (int r = 0; r < 9; r++) w[i][r] *= inv;
    }

    // ---- channel loop (8 channels)
    const float* vb = g_v + (size_t)(h * 32 + cg) * PVP + (size_t)y * PW + px0;
    float*       ob = out + (size_t)(h * 32 + cg) * NPIX + y * IMG_W + px0;
#pragma unroll 2
    for (int c = 0; c < 8; c++) {
        const float* vc = vb + (size_t)c * PVP;
        float vf[3][8];
#pragma unroll
        for (int dy = 0; dy < 3; dy++) {
            float4 a = *(const float4*)(vc + (size_t)dy * PW);
            float4 b = *(const float4*)(vc + (size_t)dy * PW + 4);
            vf[dy][0] = a.x; vf[dy][1] = a.y; vf[dy][2] = a.z; vf[dy][3] = a.w;
            vf[dy][4] = b.x; vf[dy][5] = b.y; vf[dy][6] = b.z; vf[dy][7] = b.w;
        }
        float4 o;
        float* op = (float*)&o;
#pragma unroll
        for (int i = 0; i < 4; i++) {
            float acc = 0.0f;
#pragma unroll
            for (int dy = 0; dy < 3; dy++)
#pragma unroll
                for (int dx = 0; dx < 3; dx++)
                    acc = fmaf(w[i][dy * 3 + dx], vf[dy][i + dx + 1], acc);
            op[i] = acc;
        }
        *(float4*)(ob + (size_t)c * NPIX) = o;
    }
}

// ---------------------------------------------------------------- launch
extern "C" void kernel_launch(void* const* d_in, const int* in_sizes, int n_in,
                              void* d_out, int out_size)
{
    const float* x  = (const float*)d_in[0];
    const float* wq = (const float*)d_in[1];
    const float* wk = (const float*)d_in[2];
    const float* wv = (const float*)d_in[3];
    float* out = (float*)d_out;

    cudaFuncSetAttribute(proj_fused, cudaFuncAttributeMaxDynamicSharedMemorySize, SM_TOTAL);

    dim3 wgrid(6, 8);
    prep_w<<<wgrid, 512>>>(wq, wk, wv);

    proj_fused<<<NPIX / 128, 512, SM_TOTAL>>>(x, wq, wk, wv);

    dim3 agrid(IMG_H / 4, N_HEAD, 4);        // 48 x 8 x 4 = 1536 blocks
    attn_kernel<<<agrid, 192>>>(out);
}

// round 13
// speedup vs baseline: 1.0288x; 1.0288x over previous
#include <cuda_runtime.h>
#include <cstdint>

// ---------------------------------------------------------------- constants
#define C_IN   128
#define N_HEAD 8
#define IMG_H  192
#define IMG_W  192
#define NPIX   (IMG_H * IMG_W)     // 36864
#define PW     200                 // padded row stride (floats)
#define PH     194                 // padded rows
#define PVP    (PH * PW)           // 38800 floats per plane
#define TEMPER_INV (1.0f / 16.0f)

// scratch (device globals — allocation-free per harness rules)
__device__ float g_v[256 * PVP];        // 39.7 MB, padded planes, x-offset +2
__device__ float g_s[N_HEAD * PVP];     // 1.24 MB, padded planes, x-offset +2
__device__ uint4 g_wfrag[6 * 4096];     // 384 KB: W in A-fragment form, stage order

// ---------------------------------------------------------------- SMEM map
#define SM_X     0            // X^T B-fragments: 64 KB
#define SM_W0    65536        // W A-fragments buffer 0: 64 KB
#define SM_W1    131072       // W A-fragments buffer 1: 64 KB
#define SM_TOTAL 196608

// ---------------------------------------------------------------- primitives
__device__ __forceinline__ uint32_t smem_u32(const void* p) {
    uint32_t a;
    asm("{ .reg .u64 t; cvta.to.shared.u64 t, %1; cvt.u32.u64 %0, t; }" : "=r"(a) : "l"(p));
    return a;
}

__device__ __forceinline__ uint32_t f2tf32(float f) {
    uint32_t r;
    asm("cvt.rna.tf32.f32 %0, %1;" : "=r"(r) : "f"(f));
    return r;
}

__device__ __forceinline__ void mma_tf32(float c[4], const uint32_t a[4],
                                         uint32_t b0, uint32_t b1) {
    asm volatile(
        "mma.sync.aligned.m16n8k8.row.col.f32.tf32.tf32.f32 "
        "{%0,%1,%2,%3}, {%4,%5,%6,%7}, {%8,%9}, {%0,%1,%2,%3};"
        : "+f"(c[0]), "+f"(c[1]), "+f"(c[2]), "+f"(c[3])
        : "r"(a[0]), "r"(a[1]), "r"(a[2]), "r"(a[3]), "r"(b0), "r"(b1));
}

// X^T tile (128 pixels, 128 chans) -> B-fragment-major smem.
__device__ __forceinline__ void loadX_frag(const float* __restrict__ xt,
                                           char* buf, int tid) {
    const int lane = tid & 31, kstep = tid >> 5;
    const int n = lane >> 2, kc = lane & 3;
#pragma unroll
    for (int pixgrp = 0; pixgrp < 16; pixgrp++) {
        const int pix = pixgrp * 8 + n;
        const int ch  = kstep * 8 + kc;
        uint32_t b0 = f2tf32(xt[(size_t)ch * NPIX + pix]);
        uint32_t b1 = f2tf32(xt[(size_t)(ch + 4) * NPIX + pix]);
        *(uint2*)(buf + ((pixgrp * 16 + kstep) * 32 + lane) * 8) = make_uint2(b0, b1);
    }
}

// async W stage: cp.async 16B x8 per thread, no register landing
__device__ __forceinline__ void loadW_async(int s, uint32_t dst_sm, int tid) {
    const uint4* __restrict__ src = g_wfrag + s * 4096 + tid;
    uint32_t dst = dst_sm + tid * 16;
#pragma unroll
    for (int i = 0; i < 8; i++)
        asm volatile("cp.async.cg.shared.global [%0], [%1], 16;"
                     :: "r"(dst + i * 512 * 16), "l"(src + i * 512) : "memory");
    asm volatile("cp.async.commit_group;" ::: "memory");
}
#define CP_WAIT0() asm volatile("cp.async.wait_group 0;" ::: "memory")

// C[2][4][4] += A(Abuf)[128x128] @ B(Bbuf)[128pix x 128k]^T for this warp tile.
__device__ __forceinline__ void gemm_tf32(const char* Abuf, const char* Bbuf,
                                          float C[2][4][4],
                                          int wr, int wc, int lane) {
#pragma unroll 4
    for (int kstep = 0; kstep < 16; kstep++) {
        uint32_t a[2][4];
#pragma unroll
        for (int tm = 0; tm < 2; tm++)
            *(uint4*)a[tm] =
                *(const uint4*)(Abuf + (((wr * 2 + tm) * 16 + kstep) * 32 + lane) * 16);
        uint32_t b[4][2];
#pragma unroll
        for (int tn = 0; tn < 4; tn++)
            *(uint2*)b[tn] =
                *(const uint2*)(Bbuf + (((wc * 4 + tn) * 16 + kstep) * 32 + lane) * 8);
#pragma unroll
        for (int tm = 0; tm < 2; tm++)
#pragma unroll
            for (int tn = 0; tn < 4; tn++)
                mma_tf32(C[tm][tn], a[tm], b[tn][0], b[tn][1]);
    }
}

__device__ __forceinline__ void zeroC(float C[2][4][4]) {
#pragma unroll
    for (int i = 0; i < 2; i++)
#pragma unroll
        for (int j = 0; j < 4; j++)
#pragma unroll
            for (int m = 0; m < 4; m++) C[i][j][m] = 0.0f;
}

// fused score epilogue -> padded per-head s plane (x-offset +2)
__device__ __forceinline__ void epi_s(const float C0[2][4][4], const float C1[2][4][4],
                                      int h, int p0, int wc, int lane) {
#pragma unroll
    for (int tn = 0; tn < 4; tn++) {
        float s0 = 0.0f, s1 = 0.0f;
#pragma unroll
        for (int tm = 0; tm < 2; tm++) {
            s0 += C0[tm][tn][0] * C1[tm][tn][0] + C0[tm][tn][2] * C1[tm][tn][2];
            s1 += C0[tm][tn][1] * C1[tm][tn][1] + C0[tm][tn][3] * C1[tm][tn][3];
        }
#pragma unroll
        for (int d = 4; d < 32; d <<= 1) {
            s0 += __shfl_xor_sync(0xffffffffu, s0, d);
            s1 += __shfl_xor_sync(0xffffffffu, s1, d);
        }
        if (lane < 4) {
            const int pix = p0 + wc * 32 + tn * 8 + lane * 2;
            const int y = pix / IMG_W, xx = pix - y * IMG_W;     // xx even
            *(float2*)&g_s[(size_t)h * PVP + (size_t)(y + 1) * PW + (xx + 2)] =
                make_float2(s0 * TEMPER_INV, s1 * TEMPER_INV);
        }
    }
}

// v epilogue: padded channel planes (x-offset +2 keeps 8B alignment)
__device__ __forceinline__ void sto_v(const float C[2][4][4], int cb,
                                      int p0, int wr, int wc, int lane) {
#pragma unroll
    for (int tm = 0; tm < 2; tm++)
#pragma unroll
        for (int tn = 0; tn < 4; tn++) {
            const int chan = cb + wr * 32 + tm * 16 + (lane >> 2);
            const int pix  = p0 + wc * 32 + tn * 8 + (lane & 3) * 2;
            const int y = pix / IMG_W, xx = pix - y * IMG_W;     // xx even
            float* vp = g_v + (size_t)chan * PVP + (size_t)(y + 1) * PW + (xx + 2);
            *(float2*)vp = make_float2(C[tm][tn][0], C[tm][tn][1]);
            *(float2*)(vp + (size_t)8 * PVP) = make_float2(C[tm][tn][2], C[tm][tn][3]);
        }
}

// ---------------------------------------------------------------- kernel 0
// W fp32 -> tf32 A-fragment array, stage order:
//   s=0: wq[0:128]  s=1: wk[0:128]  s=2: wq[128:256]
//   s=3: wk[128:256]  s=4: wv[0:128]  s=5: wv[128:256]
__global__ void __launch_bounds__(512)
prep_w(const float* __restrict__ wq,
       const float* __restrict__ wk,
       const float* __restrict__ wv)
{
    const int s = blockIdx.x;            // 0..5
    const int rowgrp = blockIdx.y;       // 0..7
    const float* mat = (s == 0 || s == 2) ? wq : (s == 1 || s == 3) ? wk : wv;
    const int off = (s == 2 || s == 3 || s == 5) ? 16384 : 0;

    const int tid = threadIdx.x;
    const int lane = tid & 31, kstep = tid >> 5;
    const int r = lane >> 2, c = lane & 3;

    const float* p = mat + off + (rowgrp * 16 + r) * C_IN + kstep * 8 + c;
    g_wfrag[s * 4096 + (rowgrp * 16 + kstep) * 32 + lane] =
        make_uint4(f2tf32(p[0]), f2tf32(p[8 * C_IN]),
                   f2tf32(p[4]), f2tf32(p[8 * C_IN + 4]));
}

// ---------------------------------------------------------------- kernel 1
// one CTA per 128-pixel tile; 6 weight stages staged with cp.async so the
// copy overlaps the current gemm. First 264 CTAs also zero padded borders.
__global__ void __launch_bounds__(512, 1)
proj_fused(const float* __restrict__ x,
           const float* __restrict__ wq,
           const float* __restrict__ wk,
           const float* __restrict__ wv)
{
    extern __shared__ char smem[];
    const uint32_t sb = smem_u32(smem);
    const int tid  = threadIdx.x;
    const int lane = tid & 31;
    const int wid  = tid >> 5;
    const int wr   = wid >> 2;     // 32-channel row group
    const int wc   = wid & 3;      // 32-pixel col group
    const int p0   = blockIdx.x * 128;

    // ---- issue W stage-0 copy immediately (overlaps border zero + X staging)
    loadW_async(0, sb + SM_W0, tid);

    // ---- folded border zeroing
    {
        const int bx = blockIdx.x;
        float* plane = (bx < 256) ? (g_v + (size_t)bx * PVP)
                     : (bx < 264) ? (g_s + (size_t)(bx - 256) * PVP)
                     : nullptr;
        if (plane) {
            if (tid < 200) {
                plane[tid] = 0.0f;
                plane[(size_t)193 * PW + tid] = 0.0f;
            } else if (tid >= 256 && tid < 448) {
                const int r = tid - 255;                 // 1..192
                plane[(size_t)r * PW + 1]   = 0.0f;
                plane[(size_t)r * PW + 194] = 0.0f;
            }
        }
    }

    loadX_frag(x + p0, smem + SM_X, tid);
    CP_WAIT0();
    __syncthreads();

    float C0[2][4][4], C1[2][4][4];

    // stage 0: q chans 0..127  (buf0); async-prefetch stage1 -> buf1
    loadW_async(1, sb + SM_W1, tid);
    zeroC(C0);
    gemm_tf32(smem + SM_W0, smem + SM_X, C0, wr, wc, lane);
    CP_WAIT0();
    __syncthreads();

    // stage 1: k chans 0..127  (buf1); async-prefetch stage2 -> buf0
    loadW_async(2, sb + SM_W0, tid);
    zeroC(C1);
    gemm_tf32(smem + SM_W1, smem + SM_X, C1, wr, wc, lane);
    epi_s(C0, C1, wr, p0, wc, lane);
    CP_WAIT0();
    __syncthreads();

    // stage 2: q chans 128..255 (buf0); async-prefetch stage3 -> buf1
    loadW_async(3, sb + SM_W1, tid);
    zeroC(C0);
    gemm_tf32(smem + SM_W0, smem + SM_X, C0, wr, wc, lane);
    CP_WAIT0();
    __syncthreads();

    // stage 3: k chans 128..255 (buf1); async-prefetch stage4 -> buf0
    loadW_async(4, sb + SM_W0, tid);
    zeroC(C1);
    gemm_tf32(smem + SM_W1, smem + SM_X, C1, wr, wc, lane);
    epi_s(C0, C1, 4 + wr, p0, wc, lane);
    CP_WAIT0();
    __syncthreads();

    // stage 4: v chans 0..127 (buf0); async-prefetch stage5 -> buf1
    loadW_async(5, sb + SM_W1, tid);
    zeroC(C0);
    gemm_tf32(smem + SM_W0, smem + SM_X, C0, wr, wc, lane);
    sto_v(C0, 0, p0, wr, wc, lane);
    CP_WAIT0();
    __syncthreads();

    // stage 5: v chans 128..255 (buf1)
    zeroC(C0);
    gemm_tf32(smem + SM_W1, smem + SM_X, C0, wr, wc, lane);
    sto_v(C0, 128, p0, wr, wc, lane);
}

// ---------------------------------------------------------------- kernel 2
// vectorized attn, channel-split, softmax weights in SMEM. Register cap 56
// (6 CTAs/SM): both phases fit (compute ~46 live, channel loop ~40 live),
// unlike the failed 42-reg cap. Thread owns smem column tid — no syncs.
__global__ void __launch_bounds__(192, 6)
attn_kernel(float* __restrict__ out)
{
    __shared__ float ws[36][192];

    const int tid = threadIdx.x;
    const int tx  = tid % 48;              // 48 threads per image row
    const int ty  = tid / 48;              // 4 rows per block
    const int y   = blockIdx.x * 4 + ty;
    const int h   = blockIdx.y;
    const int cg  = blockIdx.z * 8;        // channel group base
    const int px0 = tx * 4;

    // ---- s window: 3 rows x 8 cols; 4 pixels' softmax weights -> smem
    {
        float sf[3][8];
        const float* sp = g_s + (size_t)h * PVP + (size_t)y * PW + px0;
#pragma unroll
        for (int dy = 0; dy < 3; dy++) {
            float4 a = *(const float4*)(sp + (size_t)dy * PW);
            float4 b = *(const float4*)(sp + (size_t)dy * PW + 4);
            sf[dy][0] = a.x; sf[dy][1] = a.y; sf[dy][2] = a.z; sf[dy][3] = a.w;
            sf[dy][4] = b.x; sf[dy][5] = b.y; sf[dy][6] = b.z; sf[dy][7] = b.w;
        }
#pragma unroll
        for (int i = 0; i < 4; i++) {
            float m = sf[0][i + 1];
#pragma unroll
            for (int dy = 0; dy < 3; dy++)
#pragma unroll
                for (int dx = 0; dx < 3; dx++)
                    m = fmaxf(m, sf[dy][i + dx + 1]);
            float e[9], sum = 0.0f;
#pragma unroll
            for (int dy = 0; dy < 3; dy++)
#pragma unroll
                for (int dx = 0; dx < 3; dx++) {
                    float v = __expf(sf[dy][i + dx + 1] - m);
                    e[dy * 3 + dx] = v;
                    sum += v;
                }
            const float inv = 1.0f / sum;
#pragma unroll
            for (int r = 0; r < 9; r++) ws[i * 9 + r][tid] = e[r] * inv;
        }
    }

    // ---- channel loop (8 channels): 6 LDG.128 + 36 LDS + 36 FFMA + 1 STG.128
    const float* vb = g_v + (size_t)(h * 32 + cg) * PVP + (size_t)y * PW + px0;
    float*       ob = out + (size_t)(h * 32 + cg) * NPIX + y * IMG_W + px0;
#pragma unroll 2
    for (int c = 0; c < 8; c++) {
        const float* vc = vb + (size_t)c * PVP;
        float vf[3][8];
#pragma unroll
        for (int dy = 0; dy < 3; dy++) {
            float4 a = *(const float4*)(vc + (size_t)dy * PW);
            float4 b = *(const float4*)(vc + (size_t)dy * PW + 4);
            vf[dy][0] = a.x; vf[dy][1] = a.y; vf[dy][2] = a.z; vf[dy][3] = a.w;
            vf[dy][4] = b.x; vf[dy][5] = b.y; vf[dy][6] = b.z; vf[dy][7] = b.w;
        }
        float4 o;
        float* op = (float*)&o;
#pragma unroll
        for (int i = 0; i < 4; i++) {
            float acc = 0.0f;
#pragma unroll
            for (int dy = 0; dy < 3; dy++)
#pragma unroll
                for (int dx = 0; dx < 3; dx++)
                    acc = fmaf(ws[i * 9 + dy * 3 + dx][tid], vf[dy][i + dx + 1], acc);
            op[i] = acc;
        }
        *(float4*)(ob + (size_t)c * NPIX) = o;
    }
}

// ---------------------------------------------------------------- launch
extern "C" void kernel_launch(void* const* d_in, const int* in_sizes, int n_in,
                              void* d_out, int out_size)
{
    const float* x  = (const float*)d_in[0];
    const float* wq = (const float*)d_in[1];
    const float* wk = (const float*)d_in[2];
    const float* wv = (const float*)d_in[3];
    float* out = (float*)d_out;

    cudaFuncSetAttribute(proj_fused, cudaFuncAttributeMaxDynamicSharedMemorySize, SM_TOTAL);

    dim3 wgrid(6, 8);
    prep_w<<<wgrid, 512>>>(wq, wk, wv);

    proj_fused<<<NPIX / 128, 512, SM_TOTAL>>>(x, wq, wk, wv);

    dim3 agrid(IMG_H / 4, N_HEAD, 4);        // 48 x 8 x 4 = 1536 blocks
    attn_kernel<<<agrid, 192>>>(out);
}